// round 14
// baseline (speedup 1.0000x reference)
#include <cuda_runtime.h>
#include <cuda_bf16.h>

#define NN   512
#define NCH  20
#define H1   128
#define NB   32
#define NC   16
#define NKR  8            // k-range splits in k2 (256 CTAs -> 2 co-resident/SM)
#define LOG2E 1.4426950408889634f

// Scratch — transposed layouts so combine loads are coalesced
__device__ __align__(16) float g_h[NCH * NN];          // hidden, [c][i]
__device__ __align__(16) float g_M[NB * NN * NC];      // M*log2e, [b][i][c]
__device__ __align__(16) float g_opart[NKR * NB * NN]; // partials, [kr][b][i]

// ---------------------------------------------------------------------------
// K1: MLP + projection. 128 CTAs x 256 threads, 4 rows per CTA.
// ---------------------------------------------------------------------------
__global__ void __launch_bounds__(256) k1_mlp_proj(
    const float* __restrict__ x,  const float* __restrict__ W1,
    const float* __restrict__ b1, const float* __restrict__ W2,
    const float* __restrict__ b2, const float* __restrict__ T)
{
    const int i0 = blockIdx.x * 4;
    const int t  = threadIdx.x;

    __shared__ float xs[4][NCH];
    __shared__ float h1s[4][132];        // padded: conflict-free fc2 reads
    __shared__ float hs[4][NCH];
    __shared__ float W2s[H1 * NCH];      // 10 KB
    __shared__ float part[3][4 * NCH];   // fc2 k-slice partials

    // ---- prefetch everything global, all independent ----
    const int c128 = t & 127;
    float w1c[NCH], tc0[NCH], tc1[NCH];
#pragma unroll
    for (int k = 0; k < NCH; ++k) {
        w1c[k] = W1[k * H1 + c128];
        tc0[k] = T[k * NN + t];
        tc1[k] = T[k * NN + t + 256];
    }
    {
        const float4* src = reinterpret_cast<const float4*>(W2);
        float4*       dst = reinterpret_cast<float4*>(W2s);
#pragma unroll
        for (int k = t; k < H1 * NCH / 4; k += 256) dst[k] = src[k];
    }
    if (t < 4 * NCH) xs[t / NCH][t % NCH] = x[i0 * NCH + t];
    const float b1c = b1[c128];
    __syncthreads();

    // fc1 + relu: thread = (col c128, half) -> 2 rows each
    {
        const int r0 = (t >> 7) * 2;
        float a0 = b1c, a1 = a0;
#pragma unroll
        for (int k = 0; k < NCH; ++k) {
            a0 = fmaf(xs[r0 + 0][k], w1c[k], a0);
            a1 = fmaf(xs[r0 + 1][k], w1c[k], a1);
        }
        h1s[r0 + 0][c128] = fmaxf(a0, 0.f);
        h1s[r0 + 1][c128] = fmaxf(a1, 0.f);
    }
    __syncthreads();

    // fc2: 80 outputs x 3 k-slices = 240 threads
    if (t < 240) {
        const int q = t / 80, o = t % 80;
        const int r = o / NCH, c = o % NCH;
        const int k0 = q * 43, k1e = (q == 2) ? H1 : k0 + 43;
        float a = 0.f;
        for (int k = k0; k < k1e; ++k)
            a = fmaf(h1s[r][k], W2s[k * NCH + c], a);
        part[q][o] = a;
    }
    __syncthreads();
    if (t < 80) {
        const int r = t / NCH, c = t % NCH;
        float a = b2[c] + ((part[0][t] + part[1][t]) + part[2][t]);
        a = fmaxf(a, 0.f);
        hs[r][c] = a;
        g_h[c * NN + (i0 + r)] = a;      // transposed write
    }
    __syncthreads();

    // proj: per r, load hs[r][*] once -> 2 cols x 20 FMA
#pragma unroll
    for (int r = 0; r < 4; ++r) {
        float hr[NCH];
#pragma unroll
        for (int k = 0; k < NCH; ++k) hr[k] = hs[r][k];
        float m0 = 0.f, m1 = 0.f;
#pragma unroll
        for (int k = 0; k < NCH; ++k) {
            m0 = fmaf(hr[k], tc0[k], m0);
            m1 = fmaf(hr[k], tc1[k], m1);
        }
        const int colA = t, colB = t + 256;
        g_M[((colA >> 4) * NN + (i0 + r)) * NC + (colA & 15)] = m0 * LOG2E;
        g_M[((colB >> 4) * NN + (i0 + r)) * NC + (colB & 15)] = m1 * LOG2E;
    }
}

// ---------------------------------------------------------------------------
// K2: symmetric pairwise L1 + exp2, each unordered pair ONCE.
// Ms rows padded to 20 floats: LDS.128 x4 per pair, conflict-free.
// sv transposed [q][i]: stride-1 exchange, conflict-free.
// grid = (32 b, 8 k-ranges) = 256 CTAs x 512 threads (2 CTAs co-resident/SM:
// one CTA issues through the other's barrier skew).
// ---------------------------------------------------------------------------
__global__ void __launch_bounds__(512) k2_pairwise()
{
    const int b  = blockIdx.x;
    const int kr = blockIdx.y;
    const int i  = threadIdx.x;

    __shared__ float Ms[NN][20];   // 40960 B
    __shared__ float sv[4][NN];    //  8192 B  (total = 48 KB exactly)

    // mi from global (coalesced, overlaps staging)
    float4 mi0, mi1, mi2, mi3;
    {
        const float4* gm = reinterpret_cast<const float4*>(g_M + (b * NN + i) * NC);
        mi0 = gm[0]; mi1 = gm[1]; mi2 = gm[2]; mi3 = gm[3];
    }
    // stage block b into padded smem (LDG.128 + STS.128)
    {
        const float4* src = reinterpret_cast<const float4*>(g_M + b * NN * NC);
#pragma unroll
        for (int u = 0; u < 4; ++u) {
            const int idx = i + u * 512;        // float4 index
            const float4 v = src[idx];
            *reinterpret_cast<float4*>(&Ms[idx >> 2][(idx & 3) * 4]) = v;
        }
    }
    __syncthreads();

    float oacc = 0.f;
    const int kbase = kr * 32;

#pragma unroll 1
    for (int kb = 0; kb < 8; ++kb) {
#pragma unroll
        for (int q = 0; q < 4; ++q) {
            const int k = kbase + kb * 4 + q + 1;
            const int j = (i + k) & (NN - 1);
            const float4 a0 = *reinterpret_cast<const float4*>(&Ms[j][0]);
            const float4 a1 = *reinterpret_cast<const float4*>(&Ms[j][4]);
            const float4 a2 = *reinterpret_cast<const float4*>(&Ms[j][8]);
            const float4 a3 = *reinterpret_cast<const float4*>(&Ms[j][12]);
            float s0 = fabsf(mi0.x - a0.x) + fabsf(mi0.y - a0.y);
            float s1 = fabsf(mi0.z - a0.z) + fabsf(mi0.w - a0.w);
            float s2 = fabsf(mi1.x - a1.x) + fabsf(mi1.y - a1.y);
            float s3 = fabsf(mi1.z - a1.z) + fabsf(mi1.w - a1.w);
            float s4 = fabsf(mi2.x - a2.x) + fabsf(mi2.y - a2.y);
            float s5 = fabsf(mi2.z - a2.z) + fabsf(mi2.w - a2.w);
            float s6 = fabsf(mi3.x - a3.x) + fabsf(mi3.y - a3.y);
            float s7 = fabsf(mi3.z - a3.z) + fabsf(mi3.w - a3.w);
            float u0 = (s0 + s1) + (s2 + s3);
            float u1 = (s4 + s5) + (s6 + s7);
            float nd = -u0 - u1;               // -(d*log2e), M prescaled
            float e;
            asm("ex2.approx.ftz.f32 %0, %1;" : "=f"(e) : "f"(nd));
            oacc += e;                         // direct term (j = i+k)
            sv[q][i] = e;
        }
        __syncthreads();
#pragma unroll
        for (int q = 0; q < 4; ++q) {
            const int k = kbase + kb * 4 + q + 1;
            if (k < 256)                       // k==256: direct only
                oacc += sv[q][(i - k) & (NN - 1)];  // cross term (j = i-k)
        }
        __syncthreads();
    }

    g_opart[(kr * NB + b) * NN + i] = oacc;    // coalesced
}

// ---------------------------------------------------------------------------
// K3: combine partials (+1 self term), deterministic mean, final head.
// ---------------------------------------------------------------------------
__global__ void __launch_bounds__(512) k3_head(
    const float* __restrict__ W3, const float* __restrict__ b3,
    float* __restrict__ out)
{
    const int i = threadIdx.x;
    __shared__ float red[NN];

    float orow[NB];
    float s = 0.0f;
#pragma unroll
    for (int b = 0; b < NB; ++b) {
        float v = 1.0f;                        // j == i self term
#pragma unroll
        for (int q = 0; q < NKR; ++q)
            v += g_opart[(q * NB + b) * NN + i];
        orow[b] = v;
        s += v;
    }
    red[i] = s;
    __syncthreads();

#pragma unroll
    for (int st = 256; st > 0; st >>= 1) {
        if (i < st) red[i] += red[i + st];
        __syncthreads();
    }
    const float mean = red[0] * (1.0f / (float)(NN * NB));

    float acc = b3[0];
#pragma unroll
    for (int c = 0; c < NCH; ++c)
        acc = fmaf(g_h[c * NN + i], W3[c], acc);
#pragma unroll
    for (int b = 0; b < NB; ++b)
        acc = fmaf(orow[b] - mean, W3[NCH + b], acc);

    out[i] = 1.0f / (1.0f + __expf(-acc));
}

// ---------------------------------------------------------------------------
extern "C" void kernel_launch(void* const* d_in, const int* in_sizes, int n_in,
                              void* d_out, int out_size)
{
    const float* x  = (const float*)d_in[0];
    const float* W1 = (const float*)d_in[1];
    const float* b1 = (const float*)d_in[2];
    const float* W2 = (const float*)d_in[3];
    const float* b2 = (const float*)d_in[4];
    const float* T  = (const float*)d_in[5];
    const float* W3 = (const float*)d_in[6];
    const float* b3 = (const float*)d_in[7];
    float* out = (float*)d_out;

    k1_mlp_proj<<<128, 256>>>(x, W1, b1, W2, b2, T);
    dim3 g2(NB, NKR);
    k2_pairwise<<<g2, 512>>>();
    k3_head<<<1, NN>>>(W3, b3, out);
}

// round 16
// speedup vs baseline: 1.0902x; 1.0902x over previous
#include <cuda_runtime.h>
#include <cuda_bf16.h>

#define NN   512
#define NCH  20
#define H1   128
#define NB   32
#define NC   16
#define NT   16           // 512/32 row tiles
#define LOG2E 1.4426950408889634f

// Scratch
__device__ __align__(16) float g_h[NCH * NN];               // hidden, [c][i]
__device__ __align__(16) float g_M[NB * NN * NC];           // M*log2e, [b][i][c]
__device__ __align__(16) float g_part[NB * NT * NT * 32];   // [b][src][tile][lane] 1MB
__device__ __align__(16) float g_o[NB * NN];                // o features, [b][i]
__device__ float g_osum[NB];                                // per-b sums

// ---------------------------------------------------------------------------
// K1: MLP + projection. 128 CTAs x 256 threads, 4 rows per CTA. (R13, 6.6us)
// ---------------------------------------------------------------------------
__global__ void __launch_bounds__(256) k1_mlp_proj(
    const float* __restrict__ x,  const float* __restrict__ W1,
    const float* __restrict__ b1, const float* __restrict__ W2,
    const float* __restrict__ b2, const float* __restrict__ T)
{
    const int i0 = blockIdx.x * 4;
    const int t  = threadIdx.x;

    __shared__ float xs[4][NCH];
    __shared__ float h1s[4][132];
    __shared__ float hs[4][NCH];
    __shared__ float W2s[H1 * NCH];
    __shared__ float part[3][4 * NCH];

    const int c128 = t & 127;
    float w1c[NCH], tc0[NCH], tc1[NCH];
#pragma unroll
    for (int k = 0; k < NCH; ++k) {
        w1c[k] = W1[k * H1 + c128];
        tc0[k] = T[k * NN + t];
        tc1[k] = T[k * NN + t + 256];
    }
    {
        const float4* src = reinterpret_cast<const float4*>(W2);
        float4*       dst = reinterpret_cast<float4*>(W2s);
#pragma unroll
        for (int k = t; k < H1 * NCH / 4; k += 256) dst[k] = src[k];
    }
    if (t < 4 * NCH) xs[t / NCH][t % NCH] = x[i0 * NCH + t];
    const float b1c = b1[c128];
    __syncthreads();

    {
        const int r0 = (t >> 7) * 2;
        float a0 = b1c, a1 = a0;
#pragma unroll
        for (int k = 0; k < NCH; ++k) {
            a0 = fmaf(xs[r0 + 0][k], w1c[k], a0);
            a1 = fmaf(xs[r0 + 1][k], w1c[k], a1);
        }
        h1s[r0 + 0][c128] = fmaxf(a0, 0.f);
        h1s[r0 + 1][c128] = fmaxf(a1, 0.f);
    }
    __syncthreads();

    if (t < 240) {
        const int q = t / 80, o = t % 80;
        const int r = o / NCH, c = o % NCH;
        const int k0 = q * 43, k1e = (q == 2) ? H1 : k0 + 43;
        float a = 0.f;
        for (int k = k0; k < k1e; ++k)
            a = fmaf(h1s[r][k], W2s[k * NCH + c], a);
        part[q][o] = a;
    }
    __syncthreads();
    if (t < 80) {
        const int r = t / NCH, c = t % NCH;
        float a = b2[c] + ((part[0][t] + part[1][t]) + part[2][t]);
        a = fmaxf(a, 0.f);
        hs[r][c] = a;
        g_h[c * NN + (i0 + r)] = a;
    }
    __syncthreads();

#pragma unroll
    for (int r = 0; r < 4; ++r) {
        float hr[NCH];
#pragma unroll
        for (int k = 0; k < NCH; ++k) hr[k] = hs[r][k];
        float m0 = 0.f, m1 = 0.f;
#pragma unroll
        for (int k = 0; k < NCH; ++k) {
            m0 = fmaf(hr[k], tc0[k], m0);
            m1 = fmaf(hr[k], tc1[k], m1);
        }
        const int colA = t, colB = t + 256;
        g_M[((colA >> 4) * NN + (i0 + r)) * NC + (colA & 15)] = m0 * LOG2E;
        g_M[((colB >> 4) * NN + (i0 + r)) * NC + (colB & 15)] = m1 * LOG2E;
    }
}

// ---------------------------------------------------------------------------
// K2: symmetric tile-pair pairwise kernel. One warp per (b, tile-pair A<=B).
// mi (32 rows of tile A) in registers; j sweeps tile B with warp-uniform
// broadcast loads; o_j credit via fixed-order butterfly kept in lane (j&31).
// No shared memory, no barriers. grid=(32, 17) x 256 thr = 136 warps/b.
// ---------------------------------------------------------------------------
__global__ void __launch_bounds__(256) k2_tiles()
{
    const int b    = blockIdx.x;
    const int wi   = blockIdx.y * 8 + (threadIdx.x >> 5);   // 0..135
    const int lane = threadIdx.x & 31;

    // triangular decode: wi -> (A <= B)
    int A = 0, rem = wi;
    while (rem >= NT - A) { rem -= NT - A; ++A; }
    const int B = A + rem;

    const float* Mb = g_M + b * NN * NC;

    // mi = row A*32+lane (registers)
    float4 mi0, mi1, mi2, mi3;
    {
        const float4* mp = reinterpret_cast<const float4*>(Mb + (A * 32 + lane) * NC);
        mi0 = mp[0]; mi1 = mp[1]; mi2 = mp[2]; mi3 = mp[3];
    }

    float oacc = 0.f;
    const float4* rp = reinterpret_cast<const float4*>(Mb + (B * 32) * NC);

    if (A != B) {
        float cred = 0.f;
#pragma unroll 4
        for (int jj = 0; jj < 32; ++jj) {
            const float4 a0 = rp[0], a1 = rp[1], a2 = rp[2], a3 = rp[3];
            rp += 4;
            float s0 = fabsf(mi0.x - a0.x) + fabsf(mi0.y - a0.y);
            float s1 = fabsf(mi0.z - a0.z) + fabsf(mi0.w - a0.w);
            float s2 = fabsf(mi1.x - a1.x) + fabsf(mi1.y - a1.y);
            float s3 = fabsf(mi1.z - a1.z) + fabsf(mi1.w - a1.w);
            float s4 = fabsf(mi2.x - a2.x) + fabsf(mi2.y - a2.y);
            float s5 = fabsf(mi2.z - a2.z) + fabsf(mi2.w - a2.w);
            float s6 = fabsf(mi3.x - a3.x) + fabsf(mi3.y - a3.y);
            float s7 = fabsf(mi3.z - a3.z) + fabsf(mi3.w - a3.w);
            float u0 = (s0 + s1) + (s2 + s3);
            float u1 = (s4 + s5) + (s6 + s7);
            float nd = -u0 - u1;
            float e;
            asm("ex2.approx.ftz.f32 %0, %1;" : "=f"(e) : "f"(nd));
            oacc += e;                       // o_i  (i = A*32+lane)
            // butterfly: S = sum over lanes of e  (fixed order, deterministic)
            float S = e;
            S += __shfl_xor_sync(0xffffffffu, S, 16);
            S += __shfl_xor_sync(0xffffffffu, S, 8);
            S += __shfl_xor_sync(0xffffffffu, S, 4);
            S += __shfl_xor_sync(0xffffffffu, S, 2);
            S += __shfl_xor_sync(0xffffffffu, S, 1);
            if (lane == jj) cred += S;       // o_j  (j = B*32+jj)
        }
        g_part[((b * NT + B) * NT + A) * 32 + lane] = oacc;  // tile-A rows
        g_part[((b * NT + A) * NT + B) * 32 + lane] = cred;  // tile-B rows
    } else {
        // diagonal: all ordered pairs within tile incl. self (e=1)
#pragma unroll 4
        for (int jj = 0; jj < 32; ++jj) {
            const float4 a0 = rp[0], a1 = rp[1], a2 = rp[2], a3 = rp[3];
            rp += 4;
            float s0 = fabsf(mi0.x - a0.x) + fabsf(mi0.y - a0.y);
            float s1 = fabsf(mi0.z - a0.z) + fabsf(mi0.w - a0.w);
            float s2 = fabsf(mi1.x - a1.x) + fabsf(mi1.y - a1.y);
            float s3 = fabsf(mi1.z - a1.z) + fabsf(mi1.w - a1.w);
            float s4 = fabsf(mi2.x - a2.x) + fabsf(mi2.y - a2.y);
            float s5 = fabsf(mi2.z - a2.z) + fabsf(mi2.w - a2.w);
            float s6 = fabsf(mi3.x - a3.x) + fabsf(mi3.y - a3.y);
            float s7 = fabsf(mi3.z - a3.z) + fabsf(mi3.w - a3.w);
            float u0 = (s0 + s1) + (s2 + s3);
            float u1 = (s4 + s5) + (s6 + s7);
            float nd = -u0 - u1;
            float e;
            asm("ex2.approx.ftz.f32 %0, %1;" : "=f"(e) : "f"(nd));
            oacc += e;
        }
        g_part[((b * NT + A) * NT + A) * 32 + lane] = oacc;
    }
}

// ---------------------------------------------------------------------------
// K3a: per-b combine of the 16 partial slots per row; o + per-b sum.
// grid = 32 (one CTA per b) x 512.
// ---------------------------------------------------------------------------
__global__ void __launch_bounds__(512) k3a_combine()
{
    const int b = blockIdx.x;
    const int r = threadIdx.x;
    const int T = r >> 5, l = r & 31;

    float o = 0.f;
#pragma unroll
    for (int s = 0; s < NT; ++s)
        o += g_part[((b * NT + s) * NT + T) * 32 + l];
    g_o[b * NN + r] = o;

    __shared__ float red[NN];
    red[r] = o;
    __syncthreads();
#pragma unroll
    for (int st = 256; st > 0; st >>= 1) {
        if (r < st) red[r] += red[r + st];
        __syncthreads();
    }
    if (r == 0) g_osum[b] = red[0];
}

// ---------------------------------------------------------------------------
// K3b: mean + final linear + sigmoid. 1 CTA x 512.
// ---------------------------------------------------------------------------
__global__ void __launch_bounds__(512) k3b_head(
    const float* __restrict__ W3, const float* __restrict__ b3,
    float* __restrict__ out)
{
    const int i = threadIdx.x;

    float tot = 0.f;
#pragma unroll
    for (int b = 0; b < NB; ++b) tot += g_osum[b];   // uniform, L2-cached
    const float mean = tot * (1.0f / (float)(NN * NB));

    float acc = b3[0];
#pragma unroll
    for (int c = 0; c < NCH; ++c)
        acc = fmaf(g_h[c * NN + i], W3[c], acc);     // coalesced
#pragma unroll
    for (int b = 0; b < NB; ++b)
        acc = fmaf(g_o[b * NN + i] - mean, W3[NCH + b], acc);  // coalesced

    out[i] = 1.0f / (1.0f + __expf(-acc));
}

// ---------------------------------------------------------------------------
extern "C" void kernel_launch(void* const* d_in, const int* in_sizes, int n_in,
                              void* d_out, int out_size)
{
    const float* x  = (const float*)d_in[0];
    const float* W1 = (const float*)d_in[1];
    const float* b1 = (const float*)d_in[2];
    const float* W2 = (const float*)d_in[3];
    const float* b2 = (const float*)d_in[4];
    const float* T  = (const float*)d_in[5];
    const float* W3 = (const float*)d_in[6];
    const float* b3 = (const float*)d_in[7];
    float* out = (float*)d_out;

    k1_mlp_proj<<<128, 256>>>(x, W1, b1, W2, b2, T);
    dim3 g2(NB, 17);
    k2_tiles<<<g2, 256>>>();
    k3a_combine<<<NB, NN>>>();
    k3b_head<<<1, NN>>>(W3, b3, out);
}

// round 17
// speedup vs baseline: 1.1437x; 1.0491x over previous
#include <cuda_runtime.h>
#include <cuda_bf16.h>

#define NN   512
#define NCH  20
#define H1   128
#define NB   32
#define NC   16
#define NT   16           // 512/32 row tiles
#define LOG2E 1.4426950408889634f

// Scratch
__device__ __align__(16) float g_h[NCH * NN];               // hidden, [c][i]
__device__ __align__(16) float g_M[NB * NN * NC];           // M*log2e, [b][i][c]
__device__ __align__(16) float g_part[NB * NT * NT * 32];   // [b][src][tile][lane]
__device__ __align__(16) float g_o[NB * NN];                // o features, [b][i]
__device__ float g_osum[NB];                                // per-b sums

// ---------------------------------------------------------------------------
// K1: MLP + projection. 128 CTAs x 256 threads, 4 rows per CTA. (6.6us)
// ---------------------------------------------------------------------------
__global__ void __launch_bounds__(256) k1_mlp_proj(
    const float* __restrict__ x,  const float* __restrict__ W1,
    const float* __restrict__ b1, const float* __restrict__ W2,
    const float* __restrict__ b2, const float* __restrict__ T)
{
    const int i0 = blockIdx.x * 4;
    const int t  = threadIdx.x;

    __shared__ float xs[4][NCH];
    __shared__ float h1s[4][132];
    __shared__ float hs[4][NCH];
    __shared__ float W2s[H1 * NCH];
    __shared__ float part[3][4 * NCH];

    const int c128 = t & 127;
    float w1c[NCH], tc0[NCH], tc1[NCH];
#pragma unroll
    for (int k = 0; k < NCH; ++k) {
        w1c[k] = W1[k * H1 + c128];
        tc0[k] = T[k * NN + t];
        tc1[k] = T[k * NN + t + 256];
    }
    {
        const float4* src = reinterpret_cast<const float4*>(W2);
        float4*       dst = reinterpret_cast<float4*>(W2s);
#pragma unroll
        for (int k = t; k < H1 * NCH / 4; k += 256) dst[k] = src[k];
    }
    if (t < 4 * NCH) xs[t / NCH][t % NCH] = x[i0 * NCH + t];
    const float b1c = b1[c128];
    __syncthreads();

    {
        const int r0 = (t >> 7) * 2;
        float a0 = b1c, a1 = a0;
#pragma unroll
        for (int k = 0; k < NCH; ++k) {
            a0 = fmaf(xs[r0 + 0][k], w1c[k], a0);
            a1 = fmaf(xs[r0 + 1][k], w1c[k], a1);
        }
        h1s[r0 + 0][c128] = fmaxf(a0, 0.f);
        h1s[r0 + 1][c128] = fmaxf(a1, 0.f);
    }
    __syncthreads();

    if (t < 240) {
        const int q = t / 80, o = t % 80;
        const int r = o / NCH, c = o % NCH;
        const int k0 = q * 43, k1e = (q == 2) ? H1 : k0 + 43;
        float a = 0.f;
        for (int k = k0; k < k1e; ++k)
            a = fmaf(h1s[r][k], W2s[k * NCH + c], a);
        part[q][o] = a;
    }
    __syncthreads();
    if (t < 80) {
        const int r = t / NCH, c = t % NCH;
        float a = b2[c] + ((part[0][t] + part[1][t]) + part[2][t]);
        a = fmaxf(a, 0.f);
        hs[r][c] = a;
        g_h[c * NN + (i0 + r)] = a;
    }
    __syncthreads();

#pragma unroll
    for (int r = 0; r < 4; ++r) {
        float hr[NCH];
#pragma unroll
        for (int k = 0; k < NCH; ++k) hr[k] = hs[r][k];
        float m0 = 0.f, m1 = 0.f;
#pragma unroll
        for (int k = 0; k < NCH; ++k) {
            m0 = fmaf(hr[k], tc0[k], m0);
            m1 = fmaf(hr[k], tc1[k], m1);
        }
        const int colA = t, colB = t + 256;
        g_M[((colA >> 4) * NN + (i0 + r)) * NC + (colA & 15)] = m0 * LOG2E;
        g_M[((colB >> 4) * NN + (i0 + r)) * NC + (colB & 15)] = m1 * LOG2E;
    }
}

// ---------------------------------------------------------------------------
// K2: symmetric tile-pair pairwise kernel. One warp per (b, tile-pair A<=B).
// No shared memory, no barriers. grid=(32, 17) x 256 thr.
// ---------------------------------------------------------------------------
__global__ void __launch_bounds__(256) k2_tiles()
{
    const int b    = blockIdx.x;
    const int wi   = blockIdx.y * 8 + (threadIdx.x >> 5);   // 0..135
    const int lane = threadIdx.x & 31;

    int A = 0, rem = wi;
    while (rem >= NT - A) { rem -= NT - A; ++A; }
    const int B = A + rem;

    const float* Mb = g_M + b * NN * NC;

    float4 mi0, mi1, mi2, mi3;
    {
        const float4* mp = reinterpret_cast<const float4*>(Mb + (A * 32 + lane) * NC);
        mi0 = mp[0]; mi1 = mp[1]; mi2 = mp[2]; mi3 = mp[3];
    }

    float oacc = 0.f;
    const float4* rp = reinterpret_cast<const float4*>(Mb + (B * 32) * NC);

    if (A != B) {
        float cred = 0.f;
#pragma unroll 4
        for (int jj = 0; jj < 32; ++jj) {
            const float4 a0 = rp[0], a1 = rp[1], a2 = rp[2], a3 = rp[3];
            rp += 4;
            float s0 = fabsf(mi0.x - a0.x) + fabsf(mi0.y - a0.y);
            float s1 = fabsf(mi0.z - a0.z) + fabsf(mi0.w - a0.w);
            float s2 = fabsf(mi1.x - a1.x) + fabsf(mi1.y - a1.y);
            float s3 = fabsf(mi1.z - a1.z) + fabsf(mi1.w - a1.w);
            float s4 = fabsf(mi2.x - a2.x) + fabsf(mi2.y - a2.y);
            float s5 = fabsf(mi2.z - a2.z) + fabsf(mi2.w - a2.w);
            float s6 = fabsf(mi3.x - a3.x) + fabsf(mi3.y - a3.y);
            float s7 = fabsf(mi3.z - a3.z) + fabsf(mi3.w - a3.w);
            float u0 = (s0 + s1) + (s2 + s3);
            float u1 = (s4 + s5) + (s6 + s7);
            float nd = -u0 - u1;
            float e;
            asm("ex2.approx.ftz.f32 %0, %1;" : "=f"(e) : "f"(nd));
            oacc += e;
            float S = e;
            S += __shfl_xor_sync(0xffffffffu, S, 16);
            S += __shfl_xor_sync(0xffffffffu, S, 8);
            S += __shfl_xor_sync(0xffffffffu, S, 4);
            S += __shfl_xor_sync(0xffffffffu, S, 2);
            S += __shfl_xor_sync(0xffffffffu, S, 1);
            if (lane == jj) cred += S;
        }
        g_part[((b * NT + B) * NT + A) * 32 + lane] = oacc;
        g_part[((b * NT + A) * NT + B) * 32 + lane] = cred;
    } else {
#pragma unroll 4
        for (int jj = 0; jj < 32; ++jj) {
            const float4 a0 = rp[0], a1 = rp[1], a2 = rp[2], a3 = rp[3];
            rp += 4;
            float s0 = fabsf(mi0.x - a0.x) + fabsf(mi0.y - a0.y);
            float s1 = fabsf(mi0.z - a0.z) + fabsf(mi0.w - a0.w);
            float s2 = fabsf(mi1.x - a1.x) + fabsf(mi1.y - a1.y);
            float s3 = fabsf(mi1.z - a1.z) + fabsf(mi1.w - a1.w);
            float s4 = fabsf(mi2.x - a2.x) + fabsf(mi2.y - a2.y);
            float s5 = fabsf(mi2.z - a2.z) + fabsf(mi2.w - a2.w);
            float s6 = fabsf(mi3.x - a3.x) + fabsf(mi3.y - a3.y);
            float s7 = fabsf(mi3.z - a3.z) + fabsf(mi3.w - a3.w);
            float u0 = (s0 + s1) + (s2 + s3);
            float u1 = (s4 + s5) + (s6 + s7);
            float nd = -u0 - u1;
            float e;
            asm("ex2.approx.ftz.f32 %0, %1;" : "=f"(e) : "f"(nd));
            oacc += e;
        }
        g_part[((b * NT + A) * NT + A) * 32 + lane] = oacc;
    }
}

// ---------------------------------------------------------------------------
// K3a: per-b combine of partials; o + per-b sum. Prefetch-then-add.
// grid = 32 x 512.
// ---------------------------------------------------------------------------
__global__ void __launch_bounds__(512) k3a_combine()
{
    const int b = blockIdx.x;
    const int r = threadIdx.x;
    const int T = r >> 5, l = r & 31;

    float p[NT];
#pragma unroll
    for (int s = 0; s < NT; ++s)            // 16 independent LDGs, batched
        p[s] = g_part[((b * NT + s) * NT + T) * 32 + l];
    float o = 0.f;
#pragma unroll
    for (int s = 0; s < NT; ++s) o += p[s];
    g_o[b * NN + r] = o;

    __shared__ float red[NN];
    red[r] = o;
    __syncthreads();
#pragma unroll
    for (int st = 256; st > 0; st >>= 1) {
        if (r < st) red[r] += red[r + st];
        __syncthreads();
    }
    if (r == 0) g_osum[b] = red[0];
}

// ---------------------------------------------------------------------------
// K3b: mean + final linear + sigmoid.  4 CTAs x 128 threads; ALL loads
// prefetched into register arrays before any arithmetic (batched LDGs).
// ---------------------------------------------------------------------------
__global__ void __launch_bounds__(128) k3b_head(
    const float* __restrict__ W3, const float* __restrict__ b3,
    float* __restrict__ out)
{
    const int i = blockIdx.x * 128 + threadIdx.x;

    // ---- prefetch phase: all independent loads issued together ----
    float sv[NB], ov[NB], hv[NCH], w3h[NCH], w3o[NB];
#pragma unroll
    for (int b = 0; b < NB; ++b) sv[b] = g_osum[b];
#pragma unroll
    for (int b = 0; b < NB; ++b) ov[b] = g_o[b * NN + i];
#pragma unroll
    for (int c = 0; c < NCH; ++c) hv[c] = g_h[c * NN + i];
#pragma unroll
    for (int c = 0; c < NCH; ++c) w3h[c] = W3[c];
#pragma unroll
    for (int b = 0; b < NB; ++b) w3o[b] = W3[NCH + b];
    const float bias = b3[0];

    // ---- compute phase ----
    float tot = 0.f;
#pragma unroll
    for (int b = 0; b < NB; ++b) tot += sv[b];
    const float mean = tot * (1.0f / (float)(NN * NB));

    float acc = bias;
#pragma unroll
    for (int c = 0; c < NCH; ++c) acc = fmaf(hv[c], w3h[c], acc);
#pragma unroll
    for (int b = 0; b < NB; ++b)  acc = fmaf(ov[b] - mean, w3o[b], acc);

    out[i] = 1.0f / (1.0f + __expf(-acc));
}

// ---------------------------------------------------------------------------
extern "C" void kernel_launch(void* const* d_in, const int* in_sizes, int n_in,
                              void* d_out, int out_size)
{
    const float* x  = (const float*)d_in[0];
    const float* W1 = (const float*)d_in[1];
    const float* b1 = (const float*)d_in[2];
    const float* W2 = (const float*)d_in[3];
    const float* b2 = (const float*)d_in[4];
    const float* T  = (const float*)d_in[5];
    const float* W3 = (const float*)d_in[6];
    const float* b3 = (const float*)d_in[7];
    float* out = (float*)d_out;

    k1_mlp_proj<<<128, 256>>>(x, W1, b1, W2, b2, T);
    dim3 g2(NB, 17);
    k2_tiles<<<g2, 256>>>();
    k3a_combine<<<NB, NN>>>();
    k3b_head<<<4, 128>>>(W3, b3, out);
}